// round 1
// baseline (speedup 1.0000x reference)
#include <cuda_runtime.h>

// WeightedConvTranspose: out[b,o,l] = sum_{c,j} w[b,j,l] * x_t[b,c,l+j-4] * weight[o,c,j]
// with x_t = zero-insert-by-2 upsample of x.  Parity split:
//   l=2p   : j=2t,   t=0..4, x index i = p+t-2
//   l=2p+1 : j=2t+1, t=0..3, x index i = p+t-1
// w[b,j,l] = max(1 - ||coords[b,:,l+j-4] - coords[b,:,l]|| / sigma, 0), masked 0 when i OOB
// (the reference's zero-padded x_t kills those taps anyway).

#define B_      8
#define CIN_    64
#define COUT_   64
#define NIN_    16384
#define LOUT_   32768
#define KW_     9
#define PT_     64              // output pairs per tile
#define XW_     (PT_ + 4)       // 68 x positions per tile (halo 2 each side)
#define WPITCH_ 68              // padded o-pitch of transposed weight (16B aligned, 4-way STS conflict)
#define CSW_    (2 * PT_ + 8)   // 136 coords positions per tile
#define THREADS_ 512
#define TILES_PER_B_ (NIN_ / PT_)       // 256
#define NTILES_ (B_ * TILES_PER_B_)     // 2048

#define SMEM_W_FLOATS (CIN_ * KW_ * WPITCH_)    // 39168
#define SMEM_X_FLOATS (CIN_ * XW_)              // 4352
#define SMEM_C_FLOATS (3 * CSW_)                // 408
#define SMEM_BYTES ((SMEM_W_FLOATS + SMEM_X_FLOATS + SMEM_C_FLOATS) * 4)  // 175712 B

// ---- packed f32x2 helpers (sm_103a; FFMA2 only reachable via PTX) ----
static __device__ __forceinline__ unsigned long long pack2(float lo, float hi) {
    unsigned long long r;
    asm("mov.b64 %0, {%1, %2};" : "=l"(r) : "f"(lo), "f"(hi));
    return r;
}
static __device__ __forceinline__ void unpack2(unsigned long long v, float &lo, float &hi) {
    asm("mov.b64 {%0, %1}, %2;" : "=f"(lo), "=f"(hi) : "l"(v));
}
static __device__ __forceinline__ unsigned long long fma2(unsigned long long a,
                                                          unsigned long long b,
                                                          unsigned long long c) {
    unsigned long long d;
    asm("fma.rn.f32x2 %0, %1, %2, %3;" : "=l"(d) : "l"(a), "l"(b), "l"(c));
    return d;
}

__global__ void __launch_bounds__(THREADS_, 1)
wct_kernel(const float* __restrict__ x, const float* __restrict__ coords,
           const float* __restrict__ sigma, const float* __restrict__ weight,
           float* __restrict__ out) {
    extern __shared__ float smem[];
    float* w_s = smem;                      // [c][j][o] pitch WPITCH_
    float* x_s = smem + SMEM_W_FLOATS;      // [c][XW_]
    float* c_s = x_s + SMEM_X_FLOATS;       // [d][CSW_]

    const int tid = threadIdx.x;
    const int pg  = tid & 63;               // p within tile   (warp: consecutive pg)
    const int og  = tid >> 6;               // o-group 0..7    (constant within warp)
    const int o8  = og * 8;

    // One-time weight transpose: gmem [o][c][j] (coalesced read) -> smem [(c*9+j)*68 + o]
    for (int idx = tid; idx < COUT_ * CIN_ * KW_; idx += THREADS_) {
        int o = idx / (CIN_ * KW_);
        int r = idx - o * (CIN_ * KW_);     // r = c*9 + j
        w_s[r * WPITCH_ + o] = weight[idx];
    }

    const float rsig = 1.0f / sigma[0];

    for (int tile = blockIdx.x; tile < NTILES_; tile += gridDim.x) {
        __syncthreads();  // weight ready (1st iter) / previous tile's smem reads done

        const int b  = tile / TILES_PER_B_;
        const int pt = tile - b * TILES_PER_B_;
        const int p0 = pt * PT_;

        // stage x slice [64][68] : x[b, c, p0-2+k], zero-padded OOB
        const float* xb = x + (size_t)b * (CIN_ * NIN_);
        for (int idx = tid; idx < SMEM_X_FLOATS; idx += THREADS_) {
            int c = idx / XW_;
            int k = idx - c * XW_;
            int g = p0 - 2 + k;
            x_s[idx] = ((unsigned)g < (unsigned)NIN_) ? xb[c * NIN_ + g] : 0.0f;
        }
        // stage coords slice [3][136] : coords[b, d, 2*p0-4+k]
        const float* cb = coords + (size_t)b * (3 * LOUT_);
        for (int idx = tid; idx < SMEM_C_FLOATS; idx += THREADS_) {
            int d = idx / CSW_;
            int k = idx - d * CSW_;
            int m = 2 * p0 - 4 + k;
            c_s[idx] = ((unsigned)m < (unsigned)LOUT_) ? cb[d * LOUT_ + m] : 0.0f;
        }
        __syncthreads();

        const int p = p0 + pg;

        // per-thread radial window weights (even l=2p: 5 taps; odd l=2p+1: 4 taps)
        float we[5], wo[4];
        {
            const int kc = 2 * pg + 4;                    // center coords index for l=2p
            float cx = c_s[kc], cy = c_s[CSW_ + kc], cz = c_s[2 * CSW_ + kc];
            #pragma unroll
            for (int t = 0; t < 5; ++t) {
                int k = 2 * pg + 2 * t;
                float dx = c_s[k] - cx;
                float dy = c_s[CSW_ + k] - cy;
                float dz = c_s[2 * CSW_ + k] - cz;
                float nn = sqrtf(fmaf(dx, dx, fmaf(dy, dy, dz * dz)));
                float wv = fmaxf(1.0f - nn * rsig, 0.0f);
                we[t] = ((unsigned)(p + t - 2) < (unsigned)NIN_) ? wv : 0.0f;
            }
            const int ko = 2 * pg + 5;                    // center for l=2p+1
            float ox = c_s[ko], oy = c_s[CSW_ + ko], oz = c_s[2 * CSW_ + ko];
            #pragma unroll
            for (int t = 0; t < 4; ++t) {
                int k = 2 * pg + 2 * t + 2;
                float dx = c_s[k] - ox;
                float dy = c_s[CSW_ + k] - oy;
                float dz = c_s[2 * CSW_ + k] - oz;
                float nn = sqrtf(fmaf(dx, dx, fmaf(dy, dy, dz * dz)));
                float wv = fmaxf(1.0f - nn * rsig, 0.0f);
                wo[t] = ((unsigned)(p + t - 1) < (unsigned)NIN_) ? wv : 0.0f;
            }
        }

        // accumulate: 8 even outputs + 8 odd outputs as 4+4 f32x2 pairs
        unsigned long long ae0 = 0, ae1 = 0, ae2 = 0, ae3 = 0;
        unsigned long long ao0 = 0, ao1 = 0, ao2 = 0, ao3 = 0;

        const float* xrow = x_s + pg;
        const float* wrow = w_s + o8;
        for (int c = 0; c < CIN_; ++c) {
            float xv[5];
            #pragma unroll
            for (int t = 0; t < 5; ++t) xv[t] = xrow[t];

            #pragma unroll
            for (int t = 0; t < 5; ++t) {               // even taps j = 2t
                const float* wp = wrow + (2 * t) * WPITCH_;
                ulonglong2 wa = *(const ulonglong2*)(wp);
                ulonglong2 wb = *(const ulonglong2*)(wp + 4);
                float s = we[t] * xv[t];
                unsigned long long s2 = pack2(s, s);
                ae0 = fma2(s2, wa.x, ae0);
                ae1 = fma2(s2, wa.y, ae1);
                ae2 = fma2(s2, wb.x, ae2);
                ae3 = fma2(s2, wb.y, ae3);
            }
            #pragma unroll
            for (int t = 0; t < 4; ++t) {               // odd taps j = 2t+1
                const float* wp = wrow + (2 * t + 1) * WPITCH_;
                ulonglong2 wa = *(const ulonglong2*)(wp);
                ulonglong2 wb = *(const ulonglong2*)(wp + 4);
                float s = wo[t] * xv[t + 1];
                unsigned long long s2 = pack2(s, s);
                ao0 = fma2(s2, wa.x, ao0);
                ao1 = fma2(s2, wa.y, ao1);
                ao2 = fma2(s2, wb.x, ao2);
                ao3 = fma2(s2, wb.y, ao3);
            }
            xrow += XW_;
            wrow += KW_ * WPITCH_;
        }

        // store: (even,odd) interleaved -> one coalesced float2 per (o, pair)
        float* ob = out + ((size_t)(b * COUT_ + o8)) * LOUT_ + 2 * (size_t)p;
        float e0, e1, f0, f1;
        unpack2(ae0, e0, e1); unpack2(ao0, f0, f1);
        *reinterpret_cast<float2*>(ob + 0 * (size_t)LOUT_) = make_float2(e0, f0);
        *reinterpret_cast<float2*>(ob + 1 * (size_t)LOUT_) = make_float2(e1, f1);
        unpack2(ae1, e0, e1); unpack2(ao1, f0, f1);
        *reinterpret_cast<float2*>(ob + 2 * (size_t)LOUT_) = make_float2(e0, f0);
        *reinterpret_cast<float2*>(ob + 3 * (size_t)LOUT_) = make_float2(e1, f1);
        unpack2(ae2, e0, e1); unpack2(ao2, f0, f1);
        *reinterpret_cast<float2*>(ob + 4 * (size_t)LOUT_) = make_float2(e0, f0);
        *reinterpret_cast<float2*>(ob + 5 * (size_t)LOUT_) = make_float2(e1, f1);
        unpack2(ae3, e0, e1); unpack2(ao3, f0, f1);
        *reinterpret_cast<float2*>(ob + 6 * (size_t)LOUT_) = make_float2(e0, f0);
        *reinterpret_cast<float2*>(ob + 7 * (size_t)LOUT_) = make_float2(e1, f1);
    }
}

extern "C" void kernel_launch(void* const* d_in, const int* in_sizes, int n_in,
                              void* d_out, int out_size) {
    const float* x      = (const float*)d_in[0];
    const float* coords = (const float*)d_in[1];
    const float* sigma  = (const float*)d_in[2];
    const float* weight = (const float*)d_in[3];
    float* out = (float*)d_out;
    (void)in_sizes; (void)n_in; (void)out_size;

    cudaFuncSetAttribute(wct_kernel, cudaFuncAttributeMaxDynamicSharedMemorySize, SMEM_BYTES);

    int dev = 0, sms = 148;
    cudaGetDevice(&dev);
    cudaDeviceGetAttribute(&sms, cudaDevAttrMultiProcessorCount, dev);
    if (sms <= 0) sms = 148;

    wct_kernel<<<sms, THREADS_, SMEM_BYTES>>>(x, coords, sigma, weight, out);
}

// round 2
// speedup vs baseline: 1.3721x; 1.3721x over previous
#include <cuda_runtime.h>

// WeightedConvTranspose, parity-split form:
//   l=2p   : j=2t,   t=0..4, x index i = p+t-2
//   l=2p+1 : j=2t+1, t=0..3, x index i = p+t-1
// out[b,o,l] = sum_{c,taps} w[b,j,l] * x[b,c,i] * weight[o,c,j]
// w[b,j,l] = max(1 - ||coords[b,:,l+j-4] - coords[b,:,l]||/sigma, 0), 0 when i OOB.
//
// R2: register-block 2 pairs per thread (Np=2, No=8) to amortize weight LDS
// over 2x FMA work -> FMA-pipe bound instead of shared-memory bound.

#define B_      8
#define CIN_    64
#define COUT_   64
#define NIN_    16384
#define LOUT_   32768
#define KW_     9
#define PT_     128                 // output pairs per tile
#define XW_     (PT_ + 4)           // 132 x positions (halo 2 each side)
#define CSW_    (2 * PT_ + 8)       // 264 coords positions
#define THREADS_ 512
#define TILES_PER_B_ (NIN_ / PT_)   // 128
#define NTILES_ (B_ * TILES_PER_B_) // 1024

#define SMEM_W_FLOATS (CIN_ * KW_ * 64)   // 36864 (pitch 64, block-swizzled)
#define SMEM_X_FLOATS (CIN_ * XW_)        // 8448
#define SMEM_C_FLOATS (3 * CSW_)          // 792
#define SMEM_BYTES ((SMEM_W_FLOATS + SMEM_X_FLOATS + SMEM_C_FLOATS) * 4)  // ~184 KB

typedef unsigned long long ull;

static __device__ __forceinline__ ull pack2(float lo, float hi) {
    ull r;
    asm("mov.b64 %0, {%1, %2};" : "=l"(r) : "f"(lo), "f"(hi));
    return r;
}
static __device__ __forceinline__ void unpack2(ull v, float &lo, float &hi) {
    asm("mov.b64 {%0, %1}, %2;" : "=f"(lo), "=f"(hi) : "l"(v));
}
static __device__ __forceinline__ ull fma2(ull a, ull b, ull c) {
    ull d;
    asm("fma.rn.f32x2 %0, %1, %2, %3;" : "=l"(d) : "l"(a), "l"(b), "l"(c));
    return d;
}

__global__ void __launch_bounds__(THREADS_, 1)
wct_kernel(const float* __restrict__ x, const float* __restrict__ coords,
           const float* __restrict__ sigma, const float* __restrict__ weight,
           float* __restrict__ out) {
    extern __shared__ float smem[];
    float* w_s = smem;                      // [(c*9+j)*64 + swz(o,c)]
    float* x_s = smem + SMEM_W_FLOATS;      // [c][XW_]
    float* c_s = x_s + SMEM_X_FLOATS;       // [d][CSW_]

    const int tid = threadIdx.x;
    const int pg  = tid & 63;               // pair-group: handles pairs 2*pg, 2*pg+1
    const int og  = tid >> 6;               // o-group 0..7 (constant within warp)
    const int o8  = og * 8;

    // One-time weight transpose: gmem [o][c][j] -> smem [r=c*9+j][o] with a
    // per-c 16B-block rotation so STS conflicts are ~9-way (one-time) and
    // inner-loop reads stay 16B-contiguous.
    for (int idx = tid; idx < COUT_ * CIN_ * KW_; idx += THREADS_) {
        int o = idx / (CIN_ * KW_);
        int r = idx - o * (CIN_ * KW_);     // r = c*9 + j
        int c = r / KW_;
        int swz = ((((o >> 2) + c) & 15) << 2) + (o & 3);
        w_s[r * 64 + swz] = weight[idx];
    }

    const float rsig = 1.0f / sigma[0];

    for (int tile = blockIdx.x; tile < NTILES_; tile += gridDim.x) {
        __syncthreads();

        const int b  = tile / TILES_PER_B_;
        const int pt = tile - b * TILES_PER_B_;
        const int p0 = pt * PT_;

        // stage x slice [64][132]: x[b, c, p0-2+k]
        const float* xb = x + (size_t)b * (CIN_ * NIN_);
        for (int idx = tid; idx < SMEM_X_FLOATS; idx += THREADS_) {
            int c = idx / XW_;
            int k = idx - c * XW_;
            int g = p0 - 2 + k;
            x_s[idx] = ((unsigned)g < (unsigned)NIN_) ? xb[c * NIN_ + g] : 0.0f;
        }
        // stage coords slice [3][264]: coords[b, d, 2*p0-4+k]
        const float* cb = coords + (size_t)b * (3 * LOUT_);
        for (int idx = tid; idx < SMEM_C_FLOATS; idx += THREADS_) {
            int d = idx / CSW_;
            int k = idx - d * CSW_;
            int m = 2 * p0 - 4 + k;
            c_s[idx] = ((unsigned)m < (unsigned)LOUT_) ? cb[d * LOUT_ + m] : 0.0f;
        }
        __syncthreads();

        // per-thread radial window weights for 2 pairs
        float we0[5], we1[5], wo0[4], wo1[4];
        #pragma unroll
        for (int q = 0; q < 2; ++q) {
            const int pl = 2 * pg + q;
            const int p  = p0 + pl;
            const int kc = 2 * pl + 4;
            float cx = c_s[kc], cy = c_s[CSW_ + kc], cz = c_s[2 * CSW_ + kc];
            #pragma unroll
            for (int t = 0; t < 5; ++t) {
                int k = 2 * pl + 2 * t;
                float dx = c_s[k] - cx;
                float dy = c_s[CSW_ + k] - cy;
                float dz = c_s[2 * CSW_ + k] - cz;
                float nn = sqrtf(fmaf(dx, dx, fmaf(dy, dy, dz * dz)));
                float wv = fmaxf(1.0f - nn * rsig, 0.0f);
                wv = ((unsigned)(p + t - 2) < (unsigned)NIN_) ? wv : 0.0f;
                if (q == 0) we0[t] = wv; else we1[t] = wv;
            }
            const int ko = 2 * pl + 5;
            float ox = c_s[ko], oy = c_s[CSW_ + ko], oz = c_s[2 * CSW_ + ko];
            #pragma unroll
            for (int t = 0; t < 4; ++t) {
                int k = 2 * pl + 2 * t + 2;
                float dx = c_s[k] - ox;
                float dy = c_s[CSW_ + k] - oy;
                float dz = c_s[2 * CSW_ + k] - oz;
                float nn = sqrtf(fmaf(dx, dx, fmaf(dy, dy, dz * dz)));
                float wv = fmaxf(1.0f - nn * rsig, 0.0f);
                wv = ((unsigned)(p + t - 1) < (unsigned)NIN_) ? wv : 0.0f;
                if (q == 0) wo0[t] = wv; else wo1[t] = wv;
            }
        }

        // accumulators: 2 pairs x 8 outputs (even+odd), as f32x2 over outputs
        ull ae0[4] = {0,0,0,0}, ae1[4] = {0,0,0,0};
        ull ao0[4] = {0,0,0,0}, ao1[4] = {0,0,0,0};

        const float* xrow  = x_s + 2 * pg;
        const float* wbase = w_s;
        const int og2 = og << 1;

        #pragma unroll 2
        for (int c = 0; c < CIN_; ++c) {
            float2 x01 = *(const float2*)(xrow);
            float2 x23 = *(const float2*)(xrow + 2);
            float2 x45 = *(const float2*)(xrow + 4);
            float xv[6] = {x01.x, x01.y, x23.x, x23.y, x45.x, x45.y};

            const float* wp0 = wbase + (((og2     + c) & 15) << 2);
            const float* wp1 = wbase + (((og2 + 1 + c) & 15) << 2);

            #pragma unroll
            for (int t = 0; t < 5; ++t) {               // even taps j = 2t
                ulonglong2 wa = *(const ulonglong2*)(wp0 + (2 * t) * 64);
                ulonglong2 wb = *(const ulonglong2*)(wp1 + (2 * t) * 64);
                float s0 = we0[t] * xv[t];
                ull s02 = pack2(s0, s0);
                ae0[0] = fma2(s02, wa.x, ae0[0]);
                ae0[1] = fma2(s02, wa.y, ae0[1]);
                ae0[2] = fma2(s02, wb.x, ae0[2]);
                ae0[3] = fma2(s02, wb.y, ae0[3]);
                float s1 = we1[t] * xv[t + 1];
                ull s12 = pack2(s1, s1);
                ae1[0] = fma2(s12, wa.x, ae1[0]);
                ae1[1] = fma2(s12, wa.y, ae1[1]);
                ae1[2] = fma2(s12, wb.x, ae1[2]);
                ae1[3] = fma2(s12, wb.y, ae1[3]);
            }
            #pragma unroll
            for (int t = 0; t < 4; ++t) {               // odd taps j = 2t+1
                ulonglong2 wa = *(const ulonglong2*)(wp0 + (2 * t + 1) * 64);
                ulonglong2 wb = *(const ulonglong2*)(wp1 + (2 * t + 1) * 64);
                float s0 = wo0[t] * xv[t + 1];
                ull s02 = pack2(s0, s0);
                ao0[0] = fma2(s02, wa.x, ao0[0]);
                ao0[1] = fma2(s02, wa.y, ao0[1]);
                ao0[2] = fma2(s02, wb.x, ao0[2]);
                ao0[3] = fma2(s02, wb.y, ao0[3]);
                float s1 = wo1[t] * xv[t + 2];
                ull s12 = pack2(s1, s1);
                ao1[0] = fma2(s12, wa.x, ao1[0]);
                ao1[1] = fma2(s12, wa.y, ao1[1]);
                ao1[2] = fma2(s12, wb.x, ao1[2]);
                ao1[3] = fma2(s12, wb.y, ao1[3]);
            }
            xrow  += XW_;
            wbase += KW_ * 64;
        }

        // epilogue: per output one STG.128 covering l = 2*(p0+2pg) .. +3
        float E0[8], E1[8], O0[8], O1[8];
        #pragma unroll
        for (int k = 0; k < 4; ++k) {
            unpack2(ae0[k], E0[2 * k], E0[2 * k + 1]);
            unpack2(ae1[k], E1[2 * k], E1[2 * k + 1]);
            unpack2(ao0[k], O0[2 * k], O0[2 * k + 1]);
            unpack2(ao1[k], O1[2 * k], O1[2 * k + 1]);
        }
        float* ob = out + ((size_t)(b * COUT_ + o8)) * LOUT_
                        + 2 * (size_t)(p0 + 2 * pg);
        #pragma unroll
        for (int oo = 0; oo < 8; ++oo) {
            *reinterpret_cast<float4*>(ob + (size_t)oo * LOUT_) =
                make_float4(E0[oo], O0[oo], E1[oo], O1[oo]);
        }
    }
}

extern "C" void kernel_launch(void* const* d_in, const int* in_sizes, int n_in,
                              void* d_out, int out_size) {
    const float* x      = (const float*)d_in[0];
    const float* coords = (const float*)d_in[1];
    const float* sigma  = (const float*)d_in[2];
    const float* weight = (const float*)d_in[3];
    float* out = (float*)d_out;
    (void)in_sizes; (void)n_in; (void)out_size;

    cudaFuncSetAttribute(wct_kernel, cudaFuncAttributeMaxDynamicSharedMemorySize, SMEM_BYTES);

    int dev = 0, sms = 148;
    cudaGetDevice(&dev);
    cudaDeviceGetAttribute(&sms, cudaDevAttrMultiProcessorCount, dev);
    if (sms <= 0) sms = 148;

    wct_kernel<<<sms, THREADS_, SMEM_BYTES>>>(x, coords, sigma, weight, out);
}